// round 6
// baseline (speedup 1.0000x reference)
#include <cuda_runtime.h>
#include <math.h>

// Problem constants (fixed by the reference: B=4, C=256, H=W=64, Co=32)
#define BB   4
#define CC   256
#define HW   4096          // N = H*W
#define CO   32
#define OUT_ELEMS (BB*CC*HW)   // 4,194,304 floats; attn follows in d_out

// Scratch (no cudaMalloc allowed): q, k (2 MB each), v (16 MB)
__device__ float g_q[BB * CO * HW];
__device__ float g_k[BB * CO * HW];
__device__ float g_v[BB * CC * HW];

// ---------------------------------------------------------------------------
// 1x1 conv as GEMM: y[b,o,n] = sum_c W[o,c] * x[b,c,n] + bias[o]
// Block tile 64(o) x 64(n), BK=16, 256 threads, 4x4 per thread.
// ---------------------------------------------------------------------------
__global__ __launch_bounds__(256)
void conv1x1_kernel(const float* __restrict__ x, const float* __restrict__ W,
                    const float* __restrict__ bias, float* __restrict__ y, int O)
{
    const int b  = blockIdx.z;
    const int o0 = blockIdx.y * 64;
    const int n0 = blockIdx.x * 64;

    __shared__ float Ws[16][68];   // [k][o], padded
    __shared__ float Xs[16][64];   // [k][n]

    const int t  = threadIdx.x;        // 0..255
    const int ty = t >> 4;             // 0..15
    const int tx = t & 15;             // 0..15

    const float* xb = x + (size_t)b * CC * HW;
    float acc[4][4] = {};

    for (int k0 = 0; k0 < CC; k0 += 16) {
        // W tile: 64 rows (o) x 16 cols (c); one float4 per thread
        {
            int o   = t >> 2;              // 0..63
            int kk4 = (t & 3) * 4;         // 0,4,8,12
            float4 w4 = make_float4(0.f, 0.f, 0.f, 0.f);
            if (o0 + o < O)
                w4 = *reinterpret_cast<const float4*>(&W[(size_t)(o0 + o) * CC + k0 + kk4]);
            Ws[kk4 + 0][o] = w4.x;
            Ws[kk4 + 1][o] = w4.y;
            Ws[kk4 + 2][o] = w4.z;
            Ws[kk4 + 3][o] = w4.w;
        }
        // X tile: 16 rows (c) x 64 cols (n); one float4 per thread
        {
            int kk  = t >> 4;              // 0..15
            int nn4 = (t & 15) * 4;        // 0..60
            float4 x4 = *reinterpret_cast<const float4*>(&xb[(size_t)(k0 + kk) * HW + n0 + nn4]);
            *reinterpret_cast<float4*>(&Xs[kk][nn4]) = x4;
        }
        __syncthreads();

        #pragma unroll
        for (int kk = 0; kk < 16; kk++) {
            float a[4], bv_[4];
            #pragma unroll
            for (int i = 0; i < 4; i++) a[i]   = Ws[kk][ty * 4 + i];
            #pragma unroll
            for (int j = 0; j < 4; j++) bv_[j] = Xs[kk][tx * 4 + j];
            #pragma unroll
            for (int i = 0; i < 4; i++)
                #pragma unroll
                for (int j = 0; j < 4; j++)
                    acc[i][j] = fmaf(a[i], bv_[j], acc[i][j]);
        }
        __syncthreads();
    }

    #pragma unroll
    for (int i = 0; i < 4; i++) {
        int o = o0 + ty * 4 + i;
        if (o < O) {
            float bo = bias[o];
            #pragma unroll
            for (int j = 0; j < 4; j++)
                y[(size_t)b * O * HW + (size_t)o * HW + n0 + tx * 4 + j] = acc[i][j] + bo;
        }
    }
}

// ---------------------------------------------------------------------------
// scores[b,n,m] = sum_c k[b,c,n] * q[b,c,m]   (K-dim = 32, fits in smem)
// Block: 64(n) x 64(m), 256 threads, 4x4 per thread. Writes raw scores into
// the attn region of d_out (normalized in place by softmax_kernel).
// ---------------------------------------------------------------------------
__global__ __launch_bounds__(256)
void scores_kernel(float* __restrict__ attn)
{
    const int b  = blockIdx.z;
    const int n0 = blockIdx.y * 64;
    const int m0 = blockIdx.x * 64;

    __shared__ float Ks[CO][66];
    __shared__ float Qs[CO][66];

    const int t = threadIdx.x;
    const float* kb = g_k + (size_t)b * CO * HW;
    const float* qb = g_q + (size_t)b * CO * HW;

    #pragma unroll
    for (int e = 0; e < 8; e++) {
        int idx = t + e * 256;          // 0..2047
        int c   = idx >> 6;             // 0..31
        int nn  = idx & 63;             // 0..63
        Ks[c][nn] = kb[(size_t)c * HW + n0 + nn];
        Qs[c][nn] = qb[(size_t)c * HW + m0 + nn];
    }
    __syncthreads();

    const int ty = t >> 4, tx = t & 15;
    float acc[4][4] = {};
    #pragma unroll
    for (int c = 0; c < CO; c++) {
        float a[4], qv[4];
        #pragma unroll
        for (int i = 0; i < 4; i++) a[i]  = Ks[c][ty * 4 + i];
        #pragma unroll
        for (int j = 0; j < 4; j++) qv[j] = Qs[c][tx * 4 + j];
        #pragma unroll
        for (int i = 0; i < 4; i++)
            #pragma unroll
            for (int j = 0; j < 4; j++)
                acc[i][j] = fmaf(a[i], qv[j], acc[i][j]);
    }

    float* S = attn + (size_t)b * HW * HW;
    #pragma unroll
    for (int i = 0; i < 4; i++) {
        size_t rowoff = (size_t)(n0 + ty * 4 + i) * HW + m0;
        #pragma unroll
        for (int j = 0; j < 4; j++)
            S[rowoff + tx * 4 + j] = acc[i][j];
    }
}

// ---------------------------------------------------------------------------
// In-place row softmax over the last axis (rows of length 4096).
// One block (256 threads) per row; values stay in registers (16 per thread).
// ---------------------------------------------------------------------------
__global__ __launch_bounds__(256)
void softmax_kernel(float* __restrict__ attn)
{
    float* p = attn + (size_t)blockIdx.x * HW;
    const int t = threadIdx.x;

    float4 v[4];
    float mx = -1e30f;
    #pragma unroll
    for (int w = 0; w < 4; w++) {
        v[w] = *reinterpret_cast<const float4*>(&p[4 * (t + w * 256)]);
        mx = fmaxf(mx, fmaxf(fmaxf(v[w].x, v[w].y), fmaxf(v[w].z, v[w].w)));
    }

    __shared__ float warp_red[8];
    __shared__ float bcast;

    #pragma unroll
    for (int off = 16; off > 0; off >>= 1)
        mx = fmaxf(mx, __shfl_xor_sync(0xffffffffu, mx, off));
    if ((t & 31) == 0) warp_red[t >> 5] = mx;
    __syncthreads();
    if (t == 0) {
        float m = warp_red[0];
        #pragma unroll
        for (int w = 1; w < 8; w++) m = fmaxf(m, warp_red[w]);
        bcast = m;
    }
    __syncthreads();
    mx = bcast;
    __syncthreads();

    float s = 0.f;
    #pragma unroll
    for (int w = 0; w < 4; w++) {
        v[w].x = expf(v[w].x - mx);
        v[w].y = expf(v[w].y - mx);
        v[w].z = expf(v[w].z - mx);
        v[w].w = expf(v[w].w - mx);
        s += v[w].x + v[w].y + v[w].z + v[w].w;
    }

    #pragma unroll
    for (int off = 16; off > 0; off >>= 1)
        s += __shfl_xor_sync(0xffffffffu, s, off);
    if ((t & 31) == 0) warp_red[t >> 5] = s;
    __syncthreads();
    if (t == 0) {
        float tot = warp_red[0];
        #pragma unroll
        for (int w = 1; w < 8; w++) tot += warp_red[w];
        bcast = 1.0f / tot;
    }
    __syncthreads();
    float inv = bcast;

    #pragma unroll
    for (int w = 0; w < 4; w++) {
        v[w].x *= inv; v[w].y *= inv; v[w].z *= inv; v[w].w *= inv;
        *reinterpret_cast<float4*>(&p[4 * (t + w * 256)]) = v[w];
    }
}

// ---------------------------------------------------------------------------
// out[b,c,m] = gamma * sum_n v[b,c,n] * attn[b,n,m] + x[b,c,m]
// Classic SGEMM: block tile 128x128, BK=8, 256 threads, 8x8 per thread,
// global->reg prefetch to overlap load latency with FMA.
// M = C = 256 (exact multiple of 128), Ncols = K = 4096.
// ---------------------------------------------------------------------------
__global__ __launch_bounds__(256)
void av_kernel(const float* __restrict__ attn, const float* __restrict__ x,
               const float* __restrict__ gamma, float* __restrict__ out)
{
    const int b  = blockIdx.z;
    const int c0 = blockIdx.y * 128;
    const int m0 = blockIdx.x * 128;

    __shared__ float As[8][132];   // [k][c], padded (conflict-free stores)
    __shared__ float Bs[8][128];   // [k][m]

    const float* Ab = g_v  + (size_t)b * CC * HW;    // 256 x 4096 (c,n)
    const float* Bb = attn + (size_t)b * HW * HW;    // 4096 x 4096 (n,m)

    const int t    = threadIdx.x;
    const int ty   = t >> 4, tx = t & 15;
    const int arow = t >> 1;             // 0..127  (c within tile)
    const int acol = (t & 1) * 4;        // 0 or 4  (k within tile)
    const int brow = t >> 5;             // 0..7    (k within tile)
    const int bcol = (t & 31) * 4;       // 0..124  (m within tile)

    float acc[8][8] = {};

    // first prefetch
    float4 a4 = *reinterpret_cast<const float4*>(&Ab[(size_t)(c0 + arow) * HW + acol]);
    float4 b4 = *reinterpret_cast<const float4*>(&Bb[(size_t)brow * HW + m0 + bcol]);

    for (int k0 = 0; k0 < HW; k0 += 8) {
        As[acol + 0][arow] = a4.x;
        As[acol + 1][arow] = a4.y;
        As[acol + 2][arow] = a4.z;
        As[acol + 3][arow] = a4.w;
        *reinterpret_cast<float4*>(&Bs[brow][bcol]) = b4;
        __syncthreads();

        // prefetch next k-slab (clamped: last-iter loads are valid but unused)
        int kn = (k0 + 8 < HW) ? (k0 + 8) : k0;
        a4 = *reinterpret_cast<const float4*>(&Ab[(size_t)(c0 + arow) * HW + kn + acol]);
        b4 = *reinterpret_cast<const float4*>(&Bb[(size_t)(kn + brow) * HW + m0 + bcol]);

        #pragma unroll
        for (int k = 0; k < 8; k++) {
            float a[8], bb[8];
            *reinterpret_cast<float4*>(&a[0])  = *reinterpret_cast<const float4*>(&As[k][ty * 8]);
            *reinterpret_cast<float4*>(&a[4])  = *reinterpret_cast<const float4*>(&As[k][ty * 8 + 4]);
            *reinterpret_cast<float4*>(&bb[0]) = *reinterpret_cast<const float4*>(&Bs[k][tx * 8]);
            *reinterpret_cast<float4*>(&bb[4]) = *reinterpret_cast<const float4*>(&Bs[k][tx * 8 + 4]);
            #pragma unroll
            for (int i = 0; i < 8; i++)
                #pragma unroll
                for (int j = 0; j < 8; j++)
                    acc[i][j] = fmaf(a[i], bb[j], acc[i][j]);
        }
        __syncthreads();
    }

    const float g = gamma[0];
    const float* xb = x   + (size_t)b * CC * HW;
    float*       ob = out + (size_t)b * CC * HW;
    #pragma unroll
    for (int i = 0; i < 8; i++) {
        int c = c0 + ty * 8 + i;
        size_t base = (size_t)c * HW + m0 + tx * 8;
        #pragma unroll
        for (int j4 = 0; j4 < 8; j4 += 4) {
            float4 xr = *reinterpret_cast<const float4*>(&xb[base + j4]);
            float4 r;
            r.x = fmaf(g, acc[i][j4 + 0], xr.x);
            r.y = fmaf(g, acc[i][j4 + 1], xr.y);
            r.z = fmaf(g, acc[i][j4 + 2], xr.z);
            r.w = fmaf(g, acc[i][j4 + 3], xr.w);
            *reinterpret_cast<float4*>(&ob[base + j4]) = r;
        }
    }
}

// ---------------------------------------------------------------------------
extern "C" void kernel_launch(void* const* d_in, const int* in_sizes, int n_in,
                              void* d_out, int out_size)
{
    (void)in_sizes; (void)n_in; (void)out_size;
    const float* x     = (const float*)d_in[0];
    const float* Wq    = (const float*)d_in[1];
    const float* bq    = (const float*)d_in[2];
    const float* Wk    = (const float*)d_in[3];
    const float* bk    = (const float*)d_in[4];
    const float* Wv    = (const float*)d_in[5];
    const float* bv    = (const float*)d_in[6];
    const float* gamma = (const float*)d_in[7];

    float* out  = (float*)d_out;
    float* attn = out + (size_t)OUT_ELEMS;   // (B, N, N) region of d_out

    float *qp = nullptr, *kp = nullptr, *vp = nullptr;
    cudaGetSymbolAddress((void**)&qp, g_q);
    cudaGetSymbolAddress((void**)&kp, g_k);
    cudaGetSymbolAddress((void**)&vp, g_v);

    // QKV projections (1x1 convs)
    {
        dim3 blk(256);
        dim3 grid_qk(HW / 64, 1, BB);   // O=32 -> one 64-row block with guards
        dim3 grid_v (HW / 64, CC / 64, BB);
        conv1x1_kernel<<<grid_qk, blk>>>(x, Wq, bq, qp, CO);
        conv1x1_kernel<<<grid_qk, blk>>>(x, Wk, bk, kp, CO);
        conv1x1_kernel<<<grid_v,  blk>>>(x, Wv, bv, vp, CC);
    }

    // scores = K^T Q  (raw, into attn region)
    {
        dim3 blk(256);
        dim3 grid(HW / 64, HW / 64, BB);
        scores_kernel<<<grid, blk>>>(attn);
    }

    // in-place row softmax
    softmax_kernel<<<BB * HW, 256>>>(attn);

    // out = gamma * (V @ attn) + x
    {
        dim3 blk(256);
        dim3 grid(HW / 128, CC / 128, BB);
        av_kernel<<<grid, blk>>>(attn, x, gamma, out);
    }
}

// round 7
// speedup vs baseline: 1.6012x; 1.6012x over previous
#include <cuda_runtime.h>
#include <cuda_bf16.h>
#include <math.h>

// Problem constants (fixed by the reference: B=4, C=256, H=W=64, Co=32)
#define BB   4
#define CC   256
#define HW   4096          // N = H*W
#define CO   32
#define OUT_ELEMS (BB*CC*HW)   // 4,194,304 floats; attn follows in d_out

// Scratch (no cudaMalloc allowed): q, k (2 MB each), v (16 MB)
__device__ float g_q[BB * CO * HW];
__device__ float g_k[BB * CO * HW];
__device__ float g_v[BB * CC * HW];

// ---------------------------------------------------------------------------
// 1x1 conv as GEMM: y[b,o,n] = sum_c W[o,c] * x[b,c,n] + bias[o]
// ---------------------------------------------------------------------------
__global__ __launch_bounds__(256)
void conv1x1_kernel(const float* __restrict__ x, const float* __restrict__ W,
                    const float* __restrict__ bias, float* __restrict__ y, int O)
{
    const int b  = blockIdx.z;
    const int o0 = blockIdx.y * 64;
    const int n0 = blockIdx.x * 64;

    __shared__ float Ws[16][68];   // [k][o], padded
    __shared__ float Xs[16][64];   // [k][n]

    const int t  = threadIdx.x;
    const int ty = t >> 4;
    const int tx = t & 15;

    const float* xb = x + (size_t)b * CC * HW;
    float acc[4][4] = {};

    for (int k0 = 0; k0 < CC; k0 += 16) {
        {
            int o   = t >> 2;
            int kk4 = (t & 3) * 4;
            float4 w4 = make_float4(0.f, 0.f, 0.f, 0.f);
            if (o0 + o < O)
                w4 = *reinterpret_cast<const float4*>(&W[(size_t)(o0 + o) * CC + k0 + kk4]);
            Ws[kk4 + 0][o] = w4.x;
            Ws[kk4 + 1][o] = w4.y;
            Ws[kk4 + 2][o] = w4.z;
            Ws[kk4 + 3][o] = w4.w;
        }
        {
            int kk  = t >> 4;
            int nn4 = (t & 15) * 4;
            float4 x4 = *reinterpret_cast<const float4*>(&xb[(size_t)(k0 + kk) * HW + n0 + nn4]);
            *reinterpret_cast<float4*>(&Xs[kk][nn4]) = x4;
        }
        __syncthreads();

        #pragma unroll
        for (int kk = 0; kk < 16; kk++) {
            float a[4], bv_[4];
            #pragma unroll
            for (int i = 0; i < 4; i++) a[i]   = Ws[kk][ty * 4 + i];
            #pragma unroll
            for (int j = 0; j < 4; j++) bv_[j] = Xs[kk][tx * 4 + j];
            #pragma unroll
            for (int i = 0; i < 4; i++)
                #pragma unroll
                for (int j = 0; j < 4; j++)
                    acc[i][j] = fmaf(a[i], bv_[j], acc[i][j]);
        }
        __syncthreads();
    }

    #pragma unroll
    for (int i = 0; i < 4; i++) {
        int o = o0 + ty * 4 + i;
        if (o < O) {
            float bo = bias[o];
            #pragma unroll
            for (int j = 0; j < 4; j++)
                y[(size_t)b * O * HW + (size_t)o * HW + n0 + tx * 4 + j] = acc[i][j] + bo;
        }
    }
}

// ---------------------------------------------------------------------------
// scores[b,n,m] = sum_c k[b,c,n] * q[b,c,m]   (K-dim = 32 fits in smem)
// 128x128 block tile, 8x8 micro-tile per thread (halves LDS per FMA vs 4x4).
// ---------------------------------------------------------------------------
__global__ __launch_bounds__(256)
void scores_kernel(float* __restrict__ attn)
{
    const int b  = blockIdx.z;
    const int n0 = blockIdx.y * 128;
    const int m0 = blockIdx.x * 128;

    __shared__ float Ks[CO][132];
    __shared__ float Qs[CO][132];

    const int t = threadIdx.x;
    const float* kb = g_k + (size_t)b * CO * HW;
    const float* qb = g_q + (size_t)b * CO * HW;

    {
        int c  = t >> 3;             // 0..31
        int mq = (t & 7) * 4;        // 0..28
        #pragma unroll
        for (int p = 0; p < 4; p++) {
            int off = mq + p * 32;
            *reinterpret_cast<float4*>(&Ks[c][off]) =
                *reinterpret_cast<const float4*>(&kb[(size_t)c * HW + n0 + off]);
            *reinterpret_cast<float4*>(&Qs[c][off]) =
                *reinterpret_cast<const float4*>(&qb[(size_t)c * HW + m0 + off]);
        }
    }
    __syncthreads();

    const int ty = t >> 4, tx = t & 15;
    float acc[8][8] = {};
    #pragma unroll 8
    for (int c = 0; c < CO; c++) {
        float a[8], qv[8];
        *reinterpret_cast<float4*>(&a[0])  = *reinterpret_cast<const float4*>(&Ks[c][ty * 8]);
        *reinterpret_cast<float4*>(&a[4])  = *reinterpret_cast<const float4*>(&Ks[c][ty * 8 + 4]);
        *reinterpret_cast<float4*>(&qv[0]) = *reinterpret_cast<const float4*>(&Qs[c][tx * 8]);
        *reinterpret_cast<float4*>(&qv[4]) = *reinterpret_cast<const float4*>(&Qs[c][tx * 8 + 4]);
        #pragma unroll
        for (int i = 0; i < 8; i++)
            #pragma unroll
            for (int j = 0; j < 8; j++)
                acc[i][j] = fmaf(a[i], qv[j], acc[i][j]);
    }

    float* S = attn + (size_t)b * HW * HW;
    #pragma unroll
    for (int i = 0; i < 8; i++) {
        size_t base = (size_t)(n0 + ty * 8 + i) * HW + m0 + tx * 8;
        *reinterpret_cast<float4*>(&S[base])     = make_float4(acc[i][0], acc[i][1], acc[i][2], acc[i][3]);
        *reinterpret_cast<float4*>(&S[base + 4]) = make_float4(acc[i][4], acc[i][5], acc[i][6], acc[i][7]);
    }
}

// ---------------------------------------------------------------------------
// In-place row softmax over rows of length 4096. One block per row.
// ---------------------------------------------------------------------------
__global__ __launch_bounds__(256)
void softmax_kernel(float* __restrict__ attn)
{
    float* p = attn + (size_t)blockIdx.x * HW;
    const int t = threadIdx.x;

    float4 v[4];
    float mx = -1e30f;
    #pragma unroll
    for (int w = 0; w < 4; w++) {
        v[w] = *reinterpret_cast<const float4*>(&p[4 * (t + w * 256)]);
        mx = fmaxf(mx, fmaxf(fmaxf(v[w].x, v[w].y), fmaxf(v[w].z, v[w].w)));
    }

    __shared__ float warp_red[8];
    __shared__ float bcast;

    #pragma unroll
    for (int off = 16; off > 0; off >>= 1)
        mx = fmaxf(mx, __shfl_xor_sync(0xffffffffu, mx, off));
    if ((t & 31) == 0) warp_red[t >> 5] = mx;
    __syncthreads();
    if (t == 0) {
        float m = warp_red[0];
        #pragma unroll
        for (int w = 1; w < 8; w++) m = fmaxf(m, warp_red[w]);
        bcast = m;
    }
    __syncthreads();
    mx = bcast;
    __syncthreads();

    float s = 0.f;
    #pragma unroll
    for (int w = 0; w < 4; w++) {
        v[w].x = expf(v[w].x - mx);
        v[w].y = expf(v[w].y - mx);
        v[w].z = expf(v[w].z - mx);
        v[w].w = expf(v[w].w - mx);
        s += v[w].x + v[w].y + v[w].z + v[w].w;
    }

    #pragma unroll
    for (int off = 16; off > 0; off >>= 1)
        s += __shfl_xor_sync(0xffffffffu, s, off);
    if ((t & 31) == 0) warp_red[t >> 5] = s;
    __syncthreads();
    if (t == 0) {
        float tot = warp_red[0];
        #pragma unroll
        for (int w = 1; w < 8; w++) tot += warp_red[w];
        bcast = 1.0f / tot;
    }
    __syncthreads();
    float inv = bcast;

    #pragma unroll
    for (int w = 0; w < 4; w++) {
        v[w].x *= inv; v[w].y *= inv; v[w].z *= inv; v[w].w *= inv;
        *reinterpret_cast<float4*>(&p[4 * (t + w * 256)]) = v[w];
    }
}

// ---------------------------------------------------------------------------
// Tensor-core AV: out[b,c,m] = gamma * sum_n v[b,c,n]*attn[b,n,m] + x[b,c,m]
// bf16 3-term split (hi*hi + lo*hi + hi*lo) on mma.sync.m16n8k16, fp32 accum.
// Block 128(c) x 128(m), BK=32, 256 threads / 8 warps, warp tile 64x32.
// ---------------------------------------------------------------------------
__device__ __forceinline__ void mma16816(float* c, const unsigned* a, const unsigned* b)
{
    asm volatile(
        "mma.sync.aligned.m16n8k16.row.col.f32.bf16.bf16.f32 "
        "{%0,%1,%2,%3}, {%4,%5,%6,%7}, {%8,%9}, {%0,%1,%2,%3};\n"
        : "+f"(c[0]), "+f"(c[1]), "+f"(c[2]), "+f"(c[3])
        : "r"(a[0]), "r"(a[1]), "r"(a[2]), "r"(a[3]), "r"(b[0]), "r"(b[1]));
}

__device__ __forceinline__ void ldm_x4(unsigned* r, const void* p)
{
    unsigned addr = (unsigned)__cvta_generic_to_shared(p);
    asm volatile("ldmatrix.sync.aligned.m8n8.x4.shared.b16 {%0,%1,%2,%3}, [%4];\n"
                 : "=r"(r[0]), "=r"(r[1]), "=r"(r[2]), "=r"(r[3]) : "r"(addr));
}

__device__ __forceinline__ void ldm_x4_trans(unsigned* r, const void* p)
{
    unsigned addr = (unsigned)__cvta_generic_to_shared(p);
    asm volatile("ldmatrix.sync.aligned.m8n8.x4.trans.shared.b16 {%0,%1,%2,%3}, [%4];\n"
                 : "=r"(r[0]), "=r"(r[1]), "=r"(r[2]), "=r"(r[3]) : "r"(addr));
}

__device__ __forceinline__ void split_bf16(float f, __nv_bfloat16& hi, __nv_bfloat16& lo)
{
    hi = __float2bfloat16(f);
    lo = __float2bfloat16(f - __bfloat162float(hi));
}

__global__ __launch_bounds__(256)
void av_mma_kernel(const float* __restrict__ attn, const float* __restrict__ x,
                   const float* __restrict__ gamma, float* __restrict__ out)
{
    const int b  = blockIdx.z;
    const int c0 = blockIdx.y * 128;
    const int m0 = blockIdx.x * 128;

    // Padded strides: A rows 40 bf16 (80B = 5x16B, odd) and B rows 136 bf16
    // (272B = 17x16B, odd) -> per-phase conflict-free ldmatrix.
    __shared__ __nv_bfloat16 As_hi[128][40];
    __shared__ __nv_bfloat16 As_lo[128][40];
    __shared__ __nv_bfloat16 Bs_hi[32][136];
    __shared__ __nv_bfloat16 Bs_lo[32][136];

    const float* Ab = g_v  + (size_t)b * CC * HW;    // [c][n]
    const float* Bb = attn + (size_t)b * HW * HW;    // [n][m]

    const int t    = threadIdx.x;
    const int lane = t & 31;
    const int wid  = t >> 5;
    const int wm   = wid >> 2;   // 0..1  (64-row warp tile)
    const int wn   = wid & 3;    // 0..3  (32-col warp tile)

    // Global-load mapping (float4 each, 4 passes)
    const int a_row0 = t >> 3;          // + p*32
    const int a_k4   = (t & 7) * 4;
    const int b_k    = t >> 3;
    const int b_m4   = (t & 7) * 4;     // + p*32

    float c[4][4][4];
    #pragma unroll
    for (int i = 0; i < 4; i++)
        #pragma unroll
        for (int j = 0; j < 4; j++)
            #pragma unroll
            for (int e = 0; e < 4; e++) c[i][j][e] = 0.f;

    float4 av4[4], bv4[4];
    #pragma unroll
    for (int p = 0; p < 4; p++) {
        av4[p] = *reinterpret_cast<const float4*>(&Ab[(size_t)(c0 + a_row0 + p * 32) * HW + a_k4]);
        bv4[p] = *reinterpret_cast<const float4*>(&Bb[(size_t)b_k * HW + m0 + b_m4 + p * 32]);
    }

    for (int k0 = 0; k0 < HW; k0 += 32) {
        // stage store with bf16 hi/lo split
        #pragma unroll
        for (int p = 0; p < 4; p++) {
            int row = a_row0 + p * 32;
            const float* f = reinterpret_cast<const float*>(&av4[p]);
            #pragma unroll
            for (int j = 0; j < 4; j++)
                split_bf16(f[j], As_hi[row][a_k4 + j], As_lo[row][a_k4 + j]);
            int mm = b_m4 + p * 32;
            const float* g2 = reinterpret_cast<const float*>(&bv4[p]);
            #pragma unroll
            for (int j = 0; j < 4; j++)
                split_bf16(g2[j], Bs_hi[b_k][mm + j], Bs_lo[b_k][mm + j]);
        }
        __syncthreads();

        // prefetch next slab (clamped; last-iter values unused)
        int kn = (k0 + 32 < HW) ? (k0 + 32) : 0;
        #pragma unroll
        for (int p = 0; p < 4; p++) {
            av4[p] = *reinterpret_cast<const float4*>(&Ab[(size_t)(c0 + a_row0 + p * 32) * HW + kn + a_k4]);
            bv4[p] = *reinterpret_cast<const float4*>(&Bb[(size_t)(kn + b_k) * HW + m0 + b_m4 + p * 32]);
        }

        #pragma unroll
        for (int s = 0; s < 2; s++) {
            unsigned ah[4][4], al[4][4];
            #pragma unroll
            for (int mi = 0; mi < 4; mi++) {
                int ar = wm * 64 + mi * 16 + (lane & 15);
                int ac = s * 16 + (lane >> 4) * 8;
                ldm_x4(ah[mi], &As_hi[ar][ac]);
                ldm_x4(al[mi], &As_lo[ar][ac]);
            }
            unsigned bh[2][4], bl[2][4];
            #pragma unroll
            for (int nj = 0; nj < 2; nj++) {
                int br = s * 16 + (lane & 15);
                int bc = wn * 32 + nj * 16 + (lane >> 4) * 8;
                ldm_x4_trans(bh[nj], &Bs_hi[br][bc]);
                ldm_x4_trans(bl[nj], &Bs_lo[br][bc]);
            }
            #pragma unroll
            for (int mi = 0; mi < 4; mi++) {
                #pragma unroll
                for (int nt = 0; nt < 4; nt++) {
                    const unsigned* bfh = &bh[nt >> 1][(nt & 1) * 2];
                    const unsigned* bfl = &bl[nt >> 1][(nt & 1) * 2];
                    mma16816(c[mi][nt], ah[mi], bfh);   // hi*hi
                    mma16816(c[mi][nt], al[mi], bfh);   // lo*hi
                    mma16816(c[mi][nt], ah[mi], bfl);   // hi*lo
                }
            }
        }
        __syncthreads();
    }

    // Epilogue: out = gamma * acc + x
    const float g = gamma[0];
    const float* xb = x   + (size_t)b * CC * HW;
    float*       ob = out + (size_t)b * CC * HW;
    #pragma unroll
    for (int mi = 0; mi < 4; mi++) {
        #pragma unroll
        for (int nt = 0; nt < 4; nt++) {
            int r   = c0 + wm * 64 + mi * 16 + (lane >> 2);
            int col = m0 + wn * 32 + nt * 8 + (lane & 3) * 2;
            const float* cc = c[mi][nt];
            size_t i0 = (size_t)r * HW + col;
            float2 x0 = *reinterpret_cast<const float2*>(&xb[i0]);
            float2 o0;
            o0.x = fmaf(g, cc[0], x0.x);
            o0.y = fmaf(g, cc[1], x0.y);
            *reinterpret_cast<float2*>(&ob[i0]) = o0;
            size_t i1 = (size_t)(r + 8) * HW + col;
            float2 x1 = *reinterpret_cast<const float2*>(&xb[i1]);
            float2 o1;
            o1.x = fmaf(g, cc[2], x1.x);
            o1.y = fmaf(g, cc[3], x1.y);
            *reinterpret_cast<float2*>(&ob[i1]) = o1;
        }
    }
}

// ---------------------------------------------------------------------------
extern "C" void kernel_launch(void* const* d_in, const int* in_sizes, int n_in,
                              void* d_out, int out_size)
{
    (void)in_sizes; (void)n_in; (void)out_size;
    const float* x     = (const float*)d_in[0];
    const float* Wq    = (const float*)d_in[1];
    const float* bq    = (const float*)d_in[2];
    const float* Wk    = (const float*)d_in[3];
    const float* bk    = (const float*)d_in[4];
    const float* Wv    = (const float*)d_in[5];
    const float* bv    = (const float*)d_in[6];
    const float* gamma = (const float*)d_in[7];

    float* out  = (float*)d_out;
    float* attn = out + (size_t)OUT_ELEMS;

    float *qp = nullptr, *kp = nullptr, *vp = nullptr;
    cudaGetSymbolAddress((void**)&qp, g_q);
    cudaGetSymbolAddress((void**)&kp, g_k);
    cudaGetSymbolAddress((void**)&vp, g_v);

    // QKV projections
    {
        dim3 blk(256);
        dim3 grid_qk(HW / 64, 1, BB);
        dim3 grid_v (HW / 64, CC / 64, BB);
        conv1x1_kernel<<<grid_qk, blk>>>(x, Wq, bq, qp, CO);
        conv1x1_kernel<<<grid_qk, blk>>>(x, Wk, bk, kp, CO);
        conv1x1_kernel<<<grid_v,  blk>>>(x, Wv, bv, vp, CC);
    }

    // scores = K^T Q
    {
        dim3 blk(256);
        dim3 grid(HW / 128, HW / 128, BB);
        scores_kernel<<<grid, blk>>>(attn);
    }

    // in-place row softmax
    softmax_kernel<<<BB * HW, 256>>>(attn);

    // out = gamma * (V @ attn) + x  — tensor cores
    {
        dim3 blk(256);
        dim3 grid(HW / 128, CC / 128, BB);
        av_mma_kernel<<<grid, blk>>>(attn, x, gamma, out);
    }
}

// round 8
// speedup vs baseline: 2.4276x; 1.5161x over previous
#include <cuda_runtime.h>
#include <cuda_bf16.h>
#include <math.h>

// Problem constants (fixed by the reference: B=4, C=256, H=W=64, Co=32)
#define BB   4
#define CC   256
#define HW   4096          // N = H*W
#define CO   32
#define OUT_ELEMS (BB*CC*HW)   // 4,194,304 floats; attn follows in d_out

// Scratch: everything pre-split into bf16 hi/lo pairs (no fp32 copies needed)
__device__ __nv_bfloat16 g_qh[BB * CO * HW];
__device__ __nv_bfloat16 g_ql[BB * CO * HW];
__device__ __nv_bfloat16 g_kh[BB * CO * HW];
__device__ __nv_bfloat16 g_kl[BB * CO * HW];
__device__ __nv_bfloat16 g_vh[BB * CC * HW];
__device__ __nv_bfloat16 g_vl[BB * CC * HW];
__device__ __nv_bfloat16 g_ah[(size_t)BB * HW * HW];   // attn hi (128 MB)
__device__ __nv_bfloat16 g_al[(size_t)BB * HW * HW];   // attn lo (128 MB)

__device__ __forceinline__ void split_bf16(float f, __nv_bfloat16& hi, __nv_bfloat16& lo)
{
    hi = __float2bfloat16(f);
    lo = __float2bfloat16(f - __bfloat162float(hi));
}

// ---------------------------------------------------------------------------
// 1x1 conv as GEMM: y[b,o,n] = sum_c W[o,c]*x[b,c,n] + bias[o], output split
// into bf16 hi/lo (only consumers are bf16 mma kernels).
// ---------------------------------------------------------------------------
__global__ __launch_bounds__(256)
void conv1x1_kernel(const float* __restrict__ x, const float* __restrict__ W,
                    const float* __restrict__ bias,
                    __nv_bfloat16* __restrict__ yh, __nv_bfloat16* __restrict__ yl,
                    int O)
{
    const int b  = blockIdx.z;
    const int o0 = blockIdx.y * 64;
    const int n0 = blockIdx.x * 64;

    __shared__ float Ws[16][68];
    __shared__ float Xs[16][64];

    const int t  = threadIdx.x;
    const int ty = t >> 4;
    const int tx = t & 15;

    const float* xb = x + (size_t)b * CC * HW;
    float acc[4][4] = {};

    for (int k0 = 0; k0 < CC; k0 += 16) {
        {
            int o   = t >> 2;
            int kk4 = (t & 3) * 4;
            float4 w4 = make_float4(0.f, 0.f, 0.f, 0.f);
            if (o0 + o < O)
                w4 = *reinterpret_cast<const float4*>(&W[(size_t)(o0 + o) * CC + k0 + kk4]);
            Ws[kk4 + 0][o] = w4.x;
            Ws[kk4 + 1][o] = w4.y;
            Ws[kk4 + 2][o] = w4.z;
            Ws[kk4 + 3][o] = w4.w;
        }
        {
            int kk  = t >> 4;
            int nn4 = (t & 15) * 4;
            float4 x4 = *reinterpret_cast<const float4*>(&xb[(size_t)(k0 + kk) * HW + n0 + nn4]);
            *reinterpret_cast<float4*>(&Xs[kk][nn4]) = x4;
        }
        __syncthreads();

        #pragma unroll
        for (int kk = 0; kk < 16; kk++) {
            float a[4], bv_[4];
            #pragma unroll
            for (int i = 0; i < 4; i++) a[i]   = Ws[kk][ty * 4 + i];
            #pragma unroll
            for (int j = 0; j < 4; j++) bv_[j] = Xs[kk][tx * 4 + j];
            #pragma unroll
            for (int i = 0; i < 4; i++)
                #pragma unroll
                for (int j = 0; j < 4; j++)
                    acc[i][j] = fmaf(a[i], bv_[j], acc[i][j]);
        }
        __syncthreads();
    }

    #pragma unroll
    for (int i = 0; i < 4; i++) {
        int o = o0 + ty * 4 + i;
        if (o < O) {
            float bo = bias[o];
            __nv_bfloat16 h[4], l[4];
            #pragma unroll
            for (int j = 0; j < 4; j++)
                split_bf16(acc[i][j] + bo, h[j], l[j]);
            size_t base = (size_t)b * O * HW + (size_t)o * HW + n0 + tx * 4;
            *reinterpret_cast<__nv_bfloat162*>(&yh[base])     = __nv_bfloat162(h[0], h[1]);
            *reinterpret_cast<__nv_bfloat162*>(&yh[base + 2]) = __nv_bfloat162(h[2], h[3]);
            *reinterpret_cast<__nv_bfloat162*>(&yl[base])     = __nv_bfloat162(l[0], l[1]);
            *reinterpret_cast<__nv_bfloat162*>(&yl[base + 2]) = __nv_bfloat162(l[2], l[3]);
        }
    }
}

// ---------------------------------------------------------------------------
// mma helpers (fragment mappings validated by the passing R7 AV kernel)
// ---------------------------------------------------------------------------
__device__ __forceinline__ void mma16816(float* c, const unsigned* a, const unsigned* b)
{
    asm volatile(
        "mma.sync.aligned.m16n8k16.row.col.f32.bf16.bf16.f32 "
        "{%0,%1,%2,%3}, {%4,%5,%6,%7}, {%8,%9}, {%0,%1,%2,%3};\n"
        : "+f"(c[0]), "+f"(c[1]), "+f"(c[2]), "+f"(c[3])
        : "r"(a[0]), "r"(a[1]), "r"(a[2]), "r"(a[3]), "r"(b[0]), "r"(b[1]));
}

__device__ __forceinline__ void ldm_x4(unsigned* r, const void* p)
{
    unsigned addr = (unsigned)__cvta_generic_to_shared(p);
    asm volatile("ldmatrix.sync.aligned.m8n8.x4.shared.b16 {%0,%1,%2,%3}, [%4];\n"
                 : "=r"(r[0]), "=r"(r[1]), "=r"(r[2]), "=r"(r[3]) : "r"(addr));
}

__device__ __forceinline__ void ldm_x4_trans(unsigned* r, const void* p)
{
    unsigned addr = (unsigned)__cvta_generic_to_shared(p);
    asm volatile("ldmatrix.sync.aligned.m8n8.x4.trans.shared.b16 {%0,%1,%2,%3}, [%4];\n"
                 : "=r"(r[0]), "=r"(r[1]), "=r"(r[2]), "=r"(r[3]) : "r"(addr));
}

// ---------------------------------------------------------------------------
// scores[b,n,m] = sum_c k[b,c,n]*q[b,c,m] on tensor cores (3-term bf16 split).
// Block 128(n) x 128(m), K-dim = 32 (2 k16 steps). Writes fp32 scores.
// A-frag from Ks[c][n] via trans ldmatrix (regs reordered {0,2,1,3});
// B-frag from Qs[c][m] via trans ldmatrix (pairs, as in AV).
// ---------------------------------------------------------------------------
__global__ __launch_bounds__(256)
void scores_mma_kernel(float* __restrict__ attn)
{
    const int b  = blockIdx.z;
    const int n0 = blockIdx.y * 128;
    const int m0 = blockIdx.x * 128;

    __shared__ __nv_bfloat16 Ks_hi[32][136];
    __shared__ __nv_bfloat16 Ks_lo[32][136];
    __shared__ __nv_bfloat16 Qs_hi[32][136];
    __shared__ __nv_bfloat16 Qs_lo[32][136];

    const int t = threadIdx.x;
    const __nv_bfloat16* kh = g_kh + (size_t)b * CO * HW;
    const __nv_bfloat16* kl = g_kl + (size_t)b * CO * HW;
    const __nv_bfloat16* qh = g_qh + (size_t)b * CO * HW;
    const __nv_bfloat16* ql = g_ql + (size_t)b * CO * HW;

    #pragma unroll
    for (int e = 0; e < 2; e++) {
        int idx = t + e * 256;
        int r   = idx >> 4;            // 0..31 (c)
        int g   = (idx & 15) * 8;      // 0..120 (n or m)
        *reinterpret_cast<uint4*>(&Ks_hi[r][g]) = *reinterpret_cast<const uint4*>(&kh[(size_t)r * HW + n0 + g]);
        *reinterpret_cast<uint4*>(&Ks_lo[r][g]) = *reinterpret_cast<const uint4*>(&kl[(size_t)r * HW + n0 + g]);
        *reinterpret_cast<uint4*>(&Qs_hi[r][g]) = *reinterpret_cast<const uint4*>(&qh[(size_t)r * HW + m0 + g]);
        *reinterpret_cast<uint4*>(&Qs_lo[r][g]) = *reinterpret_cast<const uint4*>(&ql[(size_t)r * HW + m0 + g]);
    }
    __syncthreads();

    const int lane = t & 31;
    const int wid  = t >> 5;
    const int wm   = wid >> 2;   // 0..1 (64-row n tile)
    const int wn   = wid & 3;    // 0..3 (32-col m tile)

    float c[4][4][4];
    #pragma unroll
    for (int i = 0; i < 4; i++)
        #pragma unroll
        for (int j = 0; j < 4; j++)
            #pragma unroll
            for (int e = 0; e < 4; e++) c[i][j][e] = 0.f;

    #pragma unroll
    for (int s = 0; s < 2; s++) {
        unsigned ah[4][4], al[4][4], tmp[4];
        #pragma unroll
        for (int mi = 0; mi < 4; mi++) {
            int cr = s * 16 + (lane & 15);
            int nc = wm * 64 + mi * 16 + (lane >> 4) * 8;
            ldm_x4_trans(tmp, &Ks_hi[cr][nc]);
            ah[mi][0] = tmp[0]; ah[mi][1] = tmp[2]; ah[mi][2] = tmp[1]; ah[mi][3] = tmp[3];
            ldm_x4_trans(tmp, &Ks_lo[cr][nc]);
            al[mi][0] = tmp[0]; al[mi][1] = tmp[2]; al[mi][2] = tmp[1]; al[mi][3] = tmp[3];
        }
        unsigned bh[2][4], bl[2][4];
        #pragma unroll
        for (int nj = 0; nj < 2; nj++) {
            int cr = s * 16 + (lane & 15);
            int mc = wn * 32 + nj * 16 + (lane >> 4) * 8;
            ldm_x4_trans(bh[nj], &Qs_hi[cr][mc]);
            ldm_x4_trans(bl[nj], &Qs_lo[cr][mc]);
        }
        #pragma unroll
        for (int mi = 0; mi < 4; mi++) {
            #pragma unroll
            for (int nt = 0; nt < 4; nt++) {
                const unsigned* bfh = &bh[nt >> 1][(nt & 1) * 2];
                const unsigned* bfl = &bl[nt >> 1][(nt & 1) * 2];
                mma16816(c[mi][nt], ah[mi], bfh);
                mma16816(c[mi][nt], al[mi], bfh);
                mma16816(c[mi][nt], ah[mi], bfl);
            }
        }
    }

    float* S = attn + (size_t)b * HW * HW;
    #pragma unroll
    for (int mi = 0; mi < 4; mi++) {
        #pragma unroll
        for (int nt = 0; nt < 4; nt++) {
            int r   = n0 + wm * 64 + mi * 16 + (lane >> 2);
            int col = m0 + wn * 32 + nt * 8 + (lane & 3) * 2;
            const float* cc = c[mi][nt];
            *reinterpret_cast<float2*>(&S[(size_t)r * HW + col])       = make_float2(cc[0], cc[1]);
            *reinterpret_cast<float2*>(&S[(size_t)(r + 8) * HW + col]) = make_float2(cc[2], cc[3]);
        }
    }
}

// ---------------------------------------------------------------------------
// In-place row softmax + fused bf16 hi/lo split of attn into scratch.
// ---------------------------------------------------------------------------
__global__ __launch_bounds__(256)
void softmax_kernel(float* __restrict__ attn)
{
    const size_t rowoff = (size_t)blockIdx.x * HW;
    float* p = attn + rowoff;
    const int t = threadIdx.x;

    float4 v[4];
    float mx = -1e30f;
    #pragma unroll
    for (int w = 0; w < 4; w++) {
        v[w] = *reinterpret_cast<const float4*>(&p[4 * (t + w * 256)]);
        mx = fmaxf(mx, fmaxf(fmaxf(v[w].x, v[w].y), fmaxf(v[w].z, v[w].w)));
    }

    __shared__ float warp_red[8];
    __shared__ float bcast;

    #pragma unroll
    for (int off = 16; off > 0; off >>= 1)
        mx = fmaxf(mx, __shfl_xor_sync(0xffffffffu, mx, off));
    if ((t & 31) == 0) warp_red[t >> 5] = mx;
    __syncthreads();
    if (t == 0) {
        float m = warp_red[0];
        #pragma unroll
        for (int w = 1; w < 8; w++) m = fmaxf(m, warp_red[w]);
        bcast = m;
    }
    __syncthreads();
    mx = bcast;
    __syncthreads();

    float s = 0.f;
    #pragma unroll
    for (int w = 0; w < 4; w++) {
        v[w].x = expf(v[w].x - mx);
        v[w].y = expf(v[w].y - mx);
        v[w].z = expf(v[w].z - mx);
        v[w].w = expf(v[w].w - mx);
        s += v[w].x + v[w].y + v[w].z + v[w].w;
    }

    #pragma unroll
    for (int off = 16; off > 0; off >>= 1)
        s += __shfl_xor_sync(0xffffffffu, s, off);
    if ((t & 31) == 0) warp_red[t >> 5] = s;
    __syncthreads();
    if (t == 0) {
        float tot = warp_red[0];
        #pragma unroll
        for (int w = 1; w < 8; w++) tot += warp_red[w];
        bcast = 1.0f / tot;
    }
    __syncthreads();
    float inv = bcast;

    #pragma unroll
    for (int w = 0; w < 4; w++) {
        v[w].x *= inv; v[w].y *= inv; v[w].z *= inv; v[w].w *= inv;
        int base = 4 * (t + w * 256);
        *reinterpret_cast<float4*>(&p[base]) = v[w];

        __nv_bfloat16 h0, l0, h1, l1, h2, l2, h3, l3;
        split_bf16(v[w].x, h0, l0);
        split_bf16(v[w].y, h1, l1);
        split_bf16(v[w].z, h2, l2);
        split_bf16(v[w].w, h3, l3);
        *reinterpret_cast<__nv_bfloat162*>(&g_ah[rowoff + base])     = __nv_bfloat162(h0, h1);
        *reinterpret_cast<__nv_bfloat162*>(&g_ah[rowoff + base + 2]) = __nv_bfloat162(h2, h3);
        *reinterpret_cast<__nv_bfloat162*>(&g_al[rowoff + base])     = __nv_bfloat162(l0, l1);
        *reinterpret_cast<__nv_bfloat162*>(&g_al[rowoff + base + 2]) = __nv_bfloat162(l2, l3);
    }
}

// ---------------------------------------------------------------------------
// Tensor-core AV: out[b,c,m] = gamma * sum_n v[b,c,n]*attn[b,n,m] + x[b,c,m]
// All operands pre-split bf16 -> mainloop is pure LDG/STS/ldmatrix/mma.
// Block 128(c) x 128(m), BK=32, 8 warps, warp tile 64x32.
// ---------------------------------------------------------------------------
__global__ __launch_bounds__(256)
void av_mma_kernel(const float* __restrict__ x, const float* __restrict__ gamma,
                   float* __restrict__ out)
{
    const int b  = blockIdx.z;
    const int c0 = blockIdx.y * 128;
    const int m0 = blockIdx.x * 128;

    __shared__ __nv_bfloat16 As_hi[128][40];   // [c][k], 80B rows (5x16B, odd phase)
    __shared__ __nv_bfloat16 As_lo[128][40];
    __shared__ __nv_bfloat16 Bs_hi[32][136];   // [k][m], 272B rows (17x16B, odd)
    __shared__ __nv_bfloat16 Bs_lo[32][136];

    const __nv_bfloat16* Ah = g_vh + (size_t)b * CC * HW;
    const __nv_bfloat16* Al = g_vl + (size_t)b * CC * HW;
    const __nv_bfloat16* Bh = g_ah + (size_t)b * HW * HW;
    const __nv_bfloat16* Bl = g_al + (size_t)b * HW * HW;

    const int t    = threadIdx.x;
    const int lane = t & 31;
    const int wid  = t >> 5;
    const int wm   = wid >> 2;
    const int wn   = wid & 3;

    // A: 128x32 bf16 = 512 uint4, 2/thread: row = idx>>2, kcol = (idx&3)*8
    const int a_row = t >> 2;                 // 0..63, +64 for e=1
    const int a_kc  = (t & 3) * 8;
    // B: 32x128 bf16 = 512 uint4, 2/thread: row = idx>>4, mcol = (idx&15)*8
    const int b_row = t >> 4;                 // 0..15, +16 for e=1
    const int b_mc  = (t & 15) * 8;

    float c[4][4][4];
    #pragma unroll
    for (int i = 0; i < 4; i++)
        #pragma unroll
        for (int j = 0; j < 4; j++)
            #pragma unroll
            for (int e = 0; e < 4; e++) c[i][j][e] = 0.f;

    uint4 pa_h[2], pa_l[2], pb_h[2], pb_l[2];
    #pragma unroll
    for (int e = 0; e < 2; e++) {
        pa_h[e] = *reinterpret_cast<const uint4*>(&Ah[(size_t)(c0 + a_row + e * 64) * HW + a_kc]);
        pa_l[e] = *reinterpret_cast<const uint4*>(&Al[(size_t)(c0 + a_row + e * 64) * HW + a_kc]);
        pb_h[e] = *reinterpret_cast<const uint4*>(&Bh[(size_t)(b_row + e * 16) * HW + m0 + b_mc]);
        pb_l[e] = *reinterpret_cast<const uint4*>(&Bl[(size_t)(b_row + e * 16) * HW + m0 + b_mc]);
    }

    for (int k0 = 0; k0 < HW; k0 += 32) {
        #pragma unroll
        for (int e = 0; e < 2; e++) {
            *reinterpret_cast<uint4*>(&As_hi[a_row + e * 64][a_kc]) = pa_h[e];
            *reinterpret_cast<uint4*>(&As_lo[a_row + e * 64][a_kc]) = pa_l[e];
            *reinterpret_cast<uint4*>(&Bs_hi[b_row + e * 16][b_mc]) = pb_h[e];
            *reinterpret_cast<uint4*>(&Bs_lo[b_row + e * 16][b_mc]) = pb_l[e];
        }
        __syncthreads();

        int kn = (k0 + 32 < HW) ? (k0 + 32) : 0;
        #pragma unroll
        for (int e = 0; e < 2; e++) {
            pa_h[e] = *reinterpret_cast<const uint4*>(&Ah[(size_t)(c0 + a_row + e * 64) * HW + kn + a_kc]);
            pa_l[e] = *reinterpret_cast<const uint4*>(&Al[(size_t)(c0 + a_row + e * 64) * HW + kn + a_kc]);
            pb_h[e] = *reinterpret_cast<const uint4*>(&Bh[(size_t)(kn + b_row + e * 16) * HW + m0 + b_mc]);
            pb_l[e] = *reinterpret_cast<const uint4*>(&Bl[(size_t)(kn + b_row + e * 16) * HW + m0 + b_mc]);
        }

        #pragma unroll
        for (int s = 0; s < 2; s++) {
            unsigned ah[4][4], al[4][4];
            #pragma unroll
            for (int mi = 0; mi < 4; mi++) {
                int ar = wm * 64 + mi * 16 + (lane & 15);
                int ac = s * 16 + (lane >> 4) * 8;
                ldm_x4(ah[mi], &As_hi[ar][ac]);
                ldm_x4(al[mi], &As_lo[ar][ac]);
            }
            unsigned bh[2][4], bl[2][4];
            #pragma unroll
            for (int nj = 0; nj < 2; nj++) {
                int br = s * 16 + (lane & 15);
                int bc = wn * 32 + nj * 16 + (lane >> 4) * 8;
                ldm_x4_trans(bh[nj], &Bs_hi[br][bc]);
                ldm_x4_trans(bl[nj], &Bs_lo[br][bc]);
            }
            #pragma unroll
            for (int mi = 0; mi < 4; mi++) {
                #pragma unroll
                for (int nt = 0; nt < 4; nt++) {
                    const unsigned* bfh = &bh[nt >> 1][(nt & 1) * 2];
                    const unsigned* bfl = &bl[nt >> 1][(nt & 1) * 2];
                    mma16816(c[mi][nt], ah[mi], bfh);   // hi*hi
                    mma16816(c[mi][nt], al[mi], bfh);   // lo*hi
                    mma16816(c[mi][nt], ah[mi], bfl);   // hi*lo
                }
            }
        }
        __syncthreads();
    }

    const float g = gamma[0];
    const float* xb = x   + (size_t)b * CC * HW;
    float*       ob = out + (size_t)b * CC * HW;
    #pragma unroll
    for (int mi = 0; mi < 4; mi++) {
        #pragma unroll
        for (int nt = 0; nt < 4; nt++) {
            int r   = c0 + wm * 64 + mi * 16 + (lane >> 2);
            int col = m0 + wn * 32 + nt * 8 + (lane & 3) * 2;
            const float* cc = c[mi][nt];
            size_t i0 = (size_t)r * HW + col;
            float2 x0 = *reinterpret_cast<const float2*>(&xb[i0]);
            float2 o0;
            o0.x = fmaf(g, cc[0], x0.x);
            o0.y = fmaf(g, cc[1], x0.y);
            *reinterpret_cast<float2*>(&ob[i0]) = o0;
            size_t i1 = (size_t)(r + 8) * HW + col;
            float2 x1 = *reinterpret_cast<const float2*>(&xb[i1]);
            float2 o1;
            o1.x = fmaf(g, cc[2], x1.x);
            o1.y = fmaf(g, cc[3], x1.y);
            *reinterpret_cast<float2*>(&ob[i1]) = o1;
        }
    }
}

// ---------------------------------------------------------------------------
extern "C" void kernel_launch(void* const* d_in, const int* in_sizes, int n_in,
                              void* d_out, int out_size)
{
    (void)in_sizes; (void)n_in; (void)out_size;
    const float* x     = (const float*)d_in[0];
    const float* Wq    = (const float*)d_in[1];
    const float* bq    = (const float*)d_in[2];
    const float* Wk    = (const float*)d_in[3];
    const float* bk    = (const float*)d_in[4];
    const float* Wv    = (const float*)d_in[5];
    const float* bv    = (const float*)d_in[6];
    const float* gamma = (const float*)d_in[7];

    float* out  = (float*)d_out;
    float* attn = out + (size_t)OUT_ELEMS;

    __nv_bfloat16 *qh, *ql, *kh, *kl, *vh, *vl;
    cudaGetSymbolAddress((void**)&qh, g_qh);
    cudaGetSymbolAddress((void**)&ql, g_ql);
    cudaGetSymbolAddress((void**)&kh, g_kh);
    cudaGetSymbolAddress((void**)&kl, g_kl);
    cudaGetSymbolAddress((void**)&vh, g_vh);
    cudaGetSymbolAddress((void**)&vl, g_vl);

    // QKV projections -> bf16 hi/lo
    {
        dim3 blk(256);
        dim3 grid_qk(HW / 64, 1, BB);
        dim3 grid_v (HW / 64, CC / 64, BB);
        conv1x1_kernel<<<grid_qk, blk>>>(x, Wq, bq, qh, ql, CO);
        conv1x1_kernel<<<grid_qk, blk>>>(x, Wk, bk, kh, kl, CO);
        conv1x1_kernel<<<grid_v,  blk>>>(x, Wv, bv, vh, vl, CC);
    }

    // scores = K^T Q on tensor cores -> fp32 scores in attn region
    {
        dim3 blk(256);
        dim3 grid(HW / 128, HW / 128, BB);
        scores_mma_kernel<<<grid, blk>>>(attn);
    }

    // in-place softmax + fused bf16 hi/lo split of attn
    softmax_kernel<<<BB * HW, 256>>>(attn);

    // out = gamma * (V @ attn) + x on tensor cores
    {
        dim3 blk(256);
        dim3 grid(HW / 128, CC / 128, BB);
        av_mma_kernel<<<grid, blk>>>(x, gamma, out);
    }
}